// round 5
// baseline (speedup 1.0000x reference)
#include <cuda_runtime.h>

#define ETA   0.01f
#define EPSF  1e-8f
#define CHUNK 2048
#define TPB   256
#define SEG   8
#define MAXC  8192

__device__ float          g_aggA[MAXC];
__device__ float          g_aggB[MAXC];
__device__ volatile int   g_flag[MAXC];
__device__ int            g_ticket;
__device__ double         g_partial[MAXC];

__global__ void init_kernel(int C) {
    int i = blockIdx.x * blockDim.x + threadIdx.x;
    if (i == 0) g_ticket = 0;
    if (i < C) { g_flag[i] = 0; g_partial[i] = 0.0; }
}

__device__ __forceinline__ int padidx(int j) { return j + (j >> 3); }

__global__ void __launch_bounds__(TPB)
dsr_kernel(const float* __restrict__ W, const float* __restrict__ NR, int B) {
    __shared__ float  sR[CHUNK + CHUNK / 8];   // padded R values
    __shared__ float  sA[TPB], sB[TPB];        // scan buffers
    __shared__ float  sCarry[2];
    __shared__ int    sChunk;
    __shared__ double sRed[TPB / 32];

    const int t = threadIdx.x;
    if (t == 0) sChunk = atomicAdd(&g_ticket, 1);
    __syncthreads();
    const int c = sChunk;

    // ---------------- Phase 1: coalesced load + dot -> sR ----------------
    const float4* W4 = (const float4*)W;
    const float4* N4 = (const float4*)NR;
    const long nf4 = (long)B * 4;              // total float4 groups per array
    const long g0  = (long)c * (CHUNK * 4);

    #pragma unroll 4
    for (int i = 0; i < 32; i++) {
        long g = g0 + t + 256 * i;
        float p = 0.0f;
        if (g < nf4) {
            float4 w = W4[g];
            float4 r = N4[g];
            p = w.x * r.x + w.y * r.y + w.z * r.z + w.w * r.w;
        }
        p += __shfl_xor_sync(0xffffffffu, p, 1);
        p += __shfl_xor_sync(0xffffffffu, p, 2);
        if ((t & 3) == 0) {
            int j = (t >> 2) + 64 * i;         // local row in chunk
            sR[padidx(j)] = p;
        }
    }
    __syncthreads();

    // ---------------- Phase 2a: segment summaries + block scan ----------------
    const float q = 1.0f - ETA;
    const int segbase = t * SEG;
    float accA = 0.0f, accB = 0.0f;
    #pragma unroll
    for (int i = 0; i < SEG; i++) {
        float r = sR[padidx(segbase + i)];
        accA = accA * q + r;
        accB = accB * q + r * r;
    }
    sA[t] = accA;
    sB[t] = accB;
    __syncthreads();

    float pm = q * q; pm *= pm; pm *= pm;      // q^8
    float qk = 1.0f;                           // accumulates q^(8*t)
    for (int d = 1; d < TPB; d <<= 1) {
        if (t & d) qk *= pm;
        float a = sA[t], b = sB[t];
        if (t >= d) {
            a = fmaf(pm, sA[t - d], a);
            b = fmaf(pm, sB[t - d], b);
        }
        __syncthreads();
        sA[t] = a; sB[t] = b;
        __syncthreads();
        pm *= pm;
    }

    // ---------------- publish aggregate, fetch predecessor carry ----------------
    if (t == 0) {
        g_aggA[c] = sA[TPB - 1];
        g_aggB[c] = sB[TPB - 1];
        __threadfence();
        g_flag[c] = 1;

        float Ain = 0.0f, Bin = EPSF;
        if (c > 0) {
            while (g_flag[c - 1] == 0) { }
            __threadfence();
            // q^CHUNK ~ 1.2e-9 -> deeper carry terms are below fp32 noise
            Ain = ETA * g_aggA[c - 1];
            Bin = ETA * g_aggB[c - 1];
        }
        sCarry[0] = Ain;
        sCarry[1] = Bin;
    }

    float Wea = (t > 0) ? sA[t - 1] : 0.0f;    // exclusive weighted sums
    float Web = (t > 0) ? sB[t - 1] : 0.0f;
    __syncthreads();

    // ---------------- Phase 2b: per-segment replay of reference recurrence ----------------
    const float Ain = sCarry[0], Bin = sCarry[1];
    float A  = qk * Ain + ETA * Wea;
    float Bv = qk * Bin + ETA * Web;

    const long rowbase = (long)c * CHUNK + segbase;
    float fs = 0.0f;
    #pragma unroll
    for (int i = 0; i < SEG; i++) {
        float r   = sR[padidx(segbase + i)];
        float dA  = ETA * (r - A);
        float dB  = ETA * (r * r - Bv);
        float var = fmaxf(Bv - A * A, EPSF);
        float inv = rsqrtf(var);
        float D   = (Bv * dA - 0.5f * A * dB) * (inv * inv * inv);
        if (rowbase + i < (long)B) fs += D;
        A  += dA;
        Bv += dB;
    }

    // ---------------- deterministic block reduction ----------------
    double dsum = (double)fs;
    #pragma unroll
    for (int o = 16; o; o >>= 1) dsum += __shfl_xor_sync(0xffffffffu, dsum, o);
    if ((t & 31) == 0) sRed[t >> 5] = dsum;
    __syncthreads();
    if (t < 8) {
        double v = sRed[t];
        #pragma unroll
        for (int o = 4; o; o >>= 1) v += __shfl_xor_sync(0x000000ffu, v, o);
        if (t == 0) g_partial[c] = v;
    }
}

__global__ void finalize_kernel(float* out, int C, int B) {
    __shared__ double red[256];
    double s = 0.0;
    for (int i = threadIdx.x; i < C; i += 256) s += g_partial[i];
    red[threadIdx.x] = s;
    __syncthreads();
    for (int d = 128; d; d >>= 1) {
        if (threadIdx.x < d) red[threadIdx.x] += red[threadIdx.x + d];
        __syncthreads();
    }
    if (threadIdx.x == 0) out[0] = (float)(-red[0] / (double)B);
}

extern "C" void kernel_launch(void* const* d_in, const int* in_sizes, int n_in,
                              void* d_out, int out_size) {
    const float* w  = (const float*)d_in[0];
    const float* nr = (const float*)d_in[1];
    int B = in_sizes[0] / 16;
    int C = (B + CHUNK - 1) / CHUNK;
    if (C > MAXC) C = MAXC;  // safety; B=2e6 -> C=977

    init_kernel<<<(C + 255) / 256, 256>>>(C);
    dsr_kernel<<<C, TPB>>>(w, nr, B);
    finalize_kernel<<<1, 256>>>((float*)d_out, C, B);
}

// round 7
// speedup vs baseline: 1.1076x; 1.1076x over previous
#include <cuda_runtime.h>

#define ETA   0.01f
#define EPSF  1e-8f
#define CHUNK 2048
#define TPB   256
#define SEG   8
#define MAXC  8192

__device__ float        g_aggA[MAXC];
__device__ float        g_aggB[MAXC];
__device__ volatile int g_flag[MAXC];
__device__ int          g_ticket;
__device__ int          g_done;
__device__ double       g_partial[MAXC];

__device__ __forceinline__ int padidx(int j) { return j + (j >> 3); }

__global__ void __launch_bounds__(TPB)
dsr_kernel(const float* __restrict__ W, const float* __restrict__ NR,
           int B, int C, float* __restrict__ out) {
    __shared__ float  sR[CHUNK + CHUNK / 8];   // padded R values
    __shared__ float  wTa[8], wTb[8];          // warp totals -> scanned totals
    __shared__ float  sCarry[2];
    __shared__ int    sChunk;
    __shared__ int    sLast;
    __shared__ double sRed[TPB / 32];

    const int t    = threadIdx.x;
    const int lane = t & 31;
    const int wid  = t >> 5;

    if (t == 0) sChunk = atomicAdd(&g_ticket, 1);
    __syncthreads();
    const int c = sChunk;

    // ---------------- Phase 1: coalesced load + dot -> sR ----------------
    const float4* W4 = (const float4*)W;
    const float4* N4 = (const float4*)NR;
    const int nf4 = B * 4;                  // total float4 groups per array
    const int g0  = c * (CHUNK * 4);

    if (g0 + CHUNK * 4 <= nf4) {            // fast path: full chunk, no predicates
        #pragma unroll 8
        for (int i = 0; i < 32; i++) {
            int g = g0 + t + TPB * i;
            float4 w = W4[g];
            float4 r = N4[g];
            float p = w.x * r.x + w.y * r.y + w.z * r.z + w.w * r.w;
            p += __shfl_xor_sync(0xffffffffu, p, 1);
            p += __shfl_xor_sync(0xffffffffu, p, 2);
            if ((t & 3) == 0) sR[padidx((t >> 2) + 64 * i)] = p;
        }
    } else {                                // tail chunk only
        for (int i = 0; i < 32; i++) {
            int g = g0 + t + TPB * i;
            float p = 0.0f;
            if (g < nf4) {
                float4 w = W4[g];
                float4 r = N4[g];
                p = w.x * r.x + w.y * r.y + w.z * r.z + w.w * r.w;
            }
            p += __shfl_xor_sync(0xffffffffu, p, 1);
            p += __shfl_xor_sync(0xffffffffu, p, 2);
            if ((t & 3) == 0) sR[padidx((t >> 2) + 64 * i)] = p;
        }
    }
    __syncthreads();

    // ---------------- Phase 2a: segment sums + hierarchical shuffle scan ----
    const float q = 1.0f - ETA;
    const int segbase = t * SEG;
    float a = 0.0f, b = 0.0f;
    #pragma unroll
    for (int i = 0; i < SEG; i++) {
        float r = sR[padidx(segbase + i)];
        a = a * q + r;
        b = b * q + r * r;
    }

    // warp-level weighted inclusive scan (mult pm per step distance); pml = pm^lane
    float pm = q * q; pm *= pm; pm *= pm;   // q^8
    float m = pm, pml = 1.0f;
    #pragma unroll
    for (int o = 1; o < 32; o <<= 1) {
        if (lane & o) pml *= m;
        float au = __shfl_up_sync(0xffffffffu, a, o);
        float bu = __shfl_up_sync(0xffffffffu, b, o);
        if (lane >= o) { a = fmaf(m, au, a); b = fmaf(m, bu, b); }
        m *= m;
    }
    const float pm32 = m;                   // pm^32 = q^256

    if (lane == 31) { wTa[wid] = a; wTb[wid] = b; }
    __syncthreads();

    // cross-warp scan of the 8 warp totals (mult pm32 per step), lanes 0..7 of warp 0
    if (wid == 0 && lane < 8) {
        float ta = wTa[lane], tb = wTb[lane];
        float mm = pm32;
        #pragma unroll
        for (int o = 1; o < 8; o <<= 1) {
            float au = __shfl_up_sync(0xffu, ta, o);
            float bu = __shfl_up_sync(0xffu, tb, o);
            if (lane >= o) { ta = fmaf(mm, au, ta); tb = fmaf(mm, bu, tb); }
            mm *= mm;
        }
        wTa[lane] = ta; wTb[lane] = tb;
    }
    __syncthreads();

    // ---------------- publish aggregate, fetch predecessor carry ------------
    if (t == 0) {
        g_aggA[c] = wTa[7];                 // chunk inclusive total
        g_aggB[c] = wTb[7];
        __threadfence();                    // release: agg before flag
        g_flag[c] = 1;

        float Ain = 0.0f, Bin = EPSF;
        if (c > 0) {
            while (g_flag[c - 1] == 0) { }
            __threadfence();                // acquire: flag before agg reads
            // q^CHUNK ~ 1.2e-9 -> deeper carry terms below fp32 noise
            Ain = ETA * g_aggA[c - 1];
            Bin = ETA * g_aggB[c - 1];
        }
        sCarry[0] = Ain;
        sCarry[1] = Bin;
    }

    // exclusive prefix for this thread: Wea = E_lane + pm^lane * P_warp
    float Ea = __shfl_up_sync(0xffffffffu, a, 1);
    float Eb = __shfl_up_sync(0xffffffffu, b, 1);
    if (lane == 0) { Ea = 0.0f; Eb = 0.0f; }
    float Pa = (wid > 0) ? wTa[wid - 1] : 0.0f;
    float Pb = (wid > 0) ? wTb[wid - 1] : 0.0f;
    float Wea = fmaf(pml, Pa, Ea);
    float Web = fmaf(pml, Pb, Eb);

    // qk = pm^t = pm^lane * (pm^32)^wid
    float qk = pml, mw = pm32;
    #pragma unroll
    for (int o = 1; o < 8; o <<= 1) { if (wid & o) qk *= mw; mw *= mw; }

    __syncthreads();                        // sCarry visible
    const float Ain = sCarry[0], Bin = sCarry[1];
    float A  = fmaf(qk, Ain, ETA * Wea);
    float Bv = fmaf(qk, Bin, ETA * Web);

    // ---------------- Phase 2b: per-segment replay of reference recurrence --
    float fs = 0.0f;
    if ((c + 1) * CHUNK <= B) {             // full chunk: no row predicate
        #pragma unroll
        for (int i = 0; i < SEG; i++) {
            float r   = sR[padidx(segbase + i)];
            float dA  = ETA * (r - A);
            float dB  = ETA * (r * r - Bv);
            float var = fmaxf(Bv - A * A, EPSF);
            float inv = rsqrtf(var);
            fs += (Bv * dA - 0.5f * A * dB) * (inv * inv * inv);
            A  += dA;
            Bv += dB;
        }
    } else {
        int rowbase = c * CHUNK + segbase;
        #pragma unroll
        for (int i = 0; i < SEG; i++) {
            float r   = sR[padidx(segbase + i)];
            float dA  = ETA * (r - A);
            float dB  = ETA * (r * r - Bv);
            float var = fmaxf(Bv - A * A, EPSF);
            float inv = rsqrtf(var);
            float D   = (Bv * dA - 0.5f * A * dB) * (inv * inv * inv);
            if (rowbase + i < B) fs += D;
            A  += dA;
            Bv += dB;
        }
    }

    // ---------------- deterministic block reduction -------------------------
    double dsum = (double)fs;
    #pragma unroll
    for (int o = 16; o; o >>= 1) dsum += __shfl_xor_sync(0xffffffffu, dsum, o);
    if (lane == 0) sRed[wid] = dsum;
    __syncthreads();
    if (t < 8) {
        double v = sRed[t];
        #pragma unroll
        for (int o = 4; o; o >>= 1) v += __shfl_xor_sync(0x000000ffu, v, o);
        if (t == 0) g_partial[c] = v;
    }

    // ---------------- last block finalizes + resets state for next replay ---
    if (t == 0) {
        __threadfence();                    // g_partial[c] visible before done++
        int prev = atomicAdd(&g_done, 1);
        sLast = (prev == C - 1) ? 1 : 0;
    }
    __syncthreads();
    if (sLast) {
        __threadfence();                    // acquire all g_partial writes
        double s = 0.0;
        for (int i = t; i < C; i += TPB) s += g_partial[i];   // fixed order
        #pragma unroll
        for (int o = 16; o; o >>= 1) s += __shfl_xor_sync(0xffffffffu, s, o);
        __syncthreads();
        if (lane == 0) sRed[wid] = s;
        __syncthreads();
        if (t < 8) {
            double v = sRed[t];
            #pragma unroll
            for (int o = 4; o; o >>= 1) v += __shfl_xor_sync(0x000000ffu, v, o);
            if (t == 0) out[0] = (float)(-v / (double)B);
        }
        // reset inter-block state so the next graph replay starts clean
        for (int i = t; i < C; i += TPB) g_flag[i] = 0;
        if (t == 0) { g_ticket = 0; g_done = 0; }
    }
}

extern "C" void kernel_launch(void* const* d_in, const int* in_sizes, int n_in,
                              void* d_out, int out_size) {
    const float* w  = (const float*)d_in[0];
    const float* nr = (const float*)d_in[1];
    int B = in_sizes[0] / 16;
    int C = (B + CHUNK - 1) / CHUNK;
    if (C > MAXC) C = MAXC;                 // safety; B=2e6 -> C=977

    dsr_kernel<<<C, TPB>>>(w, nr, B, C, (float*)d_out);
}